// round 5
// baseline (speedup 1.0000x reference)
#include <cuda_runtime.h>
#include <cuda_bf16.h>
#include <cstdint>

// soft_to_hard_quantize: N=524288 vectors of D=16 floats, M=64 codewords.
// logit_m (log2 domain) = 10*log2e*dot(x,r_m) - 5*log2e*||r_m||^2  (||x||^2 cancels)
// z = sum_m exp2(logit_m - max) * r_m / sum_m exp2(...)
//
// Codebook in __constant__ memory (uniform LDCU path). V=2 vectors per thread:
// each constant load feeds two FFMA2s (halves LDC pressure per vector) and the
// two independent chains give the ILP needed at low occupancy. Full unroll of
// both m-loops keeps the 2x64 logits in registers. No launch_bounds cap (the
// R2 spill disaster came from capping regs at 128).

#define MCODE 64
#define DVEC  16
#define TPB   128
#define VPT   2

typedef unsigned long long u64;

struct Codebook {
    float slog[MCODE][DVEC];  // 10*log2(e) * r_m[i]   (logit dot operand)
    float b2p[MCODE][2];      // { -5*log2(e)*||r_m||^2, 0 }  (acc init pair)
    float cw[MCODE][DVEC];    // raw r_m[i]            (z accumulation operand)
};

__device__   Codebook g_cb;   // staging, written by prep kernel
__constant__ Codebook c_cb;   // read by main kernel

__global__ void prep_kernel(const float* __restrict__ ref) {
    const int m = threadIdx.x;  // 64 threads
    float s = 0.0f;
    #pragma unroll
    for (int i = 0; i < DVEC; i++) {
        float r = ref[m * DVEC + i];
        g_cb.cw[m][i]   = r;
        g_cb.slog[m][i] = 14.426950408889634f * r;   // 10*log2(e)
        s = fmaf(r, r, s);
    }
    g_cb.b2p[m][0] = -7.2134752044448169f * s;       // -5*log2(e)
    g_cb.b2p[m][1] = 0.0f;
}

__device__ __forceinline__ u64 fma2(u64 a, u64 b, u64 c) {
    u64 d;
    asm("fma.rn.f32x2 %0, %1, %2, %3;" : "=l"(d) : "l"(a), "l"(b), "l"(c));
    return d;
}
__device__ __forceinline__ u64 mul2(u64 a, u64 b) {
    u64 d;
    asm("mul.rn.f32x2 %0, %1, %2;" : "=l"(d) : "l"(a), "l"(b));
    return d;
}
__device__ __forceinline__ u64 pack2(float lo, float hi) {
    u64 r;
    asm("mov.b64 %0, {%1, %2};" : "=l"(r) : "f"(lo), "f"(hi));
    return r;
}
__device__ __forceinline__ void unpack2(u64 v, float& lo, float& hi) {
    asm("mov.b64 {%0, %1}, %2;" : "=f"(lo), "=f"(hi) : "l"(v));
}
__device__ __forceinline__ float ex2f(float x) {
    float r;
    asm("ex2.approx.ftz.f32 %0, %1;" : "=f"(r) : "f"(x));
    return r;
}
__device__ __forceinline__ float rcpf(float x) {
    float r;
    asm("rcp.approx.ftz.f32 %0, %1;" : "=f"(r) : "f"(x));
    return r;
}
__device__ __forceinline__ u64 cpair(const float* p) {
    return *reinterpret_cast<const u64*>(p);
}

__global__ __launch_bounds__(TPB)
void stq_kernel(const float* __restrict__ x,
                float* __restrict__ out,
                int nvec) {
    const int v0 = blockIdx.x * (TPB * VPT) + threadIdx.x;  // vector A
    const int v1 = v0 + TPB;                                 // vector B
    // nvec (524288) is an exact multiple of TPB*VPT; no tail handling needed.

    // Load both vectors: 16 floats = 8 packed pairs each (4 x LDG.128).
    u64 xa[8], xb[8];
    {
        const ulonglong2* pa = reinterpret_cast<const ulonglong2*>(x + (size_t)v0 * DVEC);
        const ulonglong2* pb = reinterpret_cast<const ulonglong2*>(x + (size_t)v1 * DVEC);
        #pragma unroll
        for (int i = 0; i < 4; i++) {
            ulonglong2 ta = pa[i];
            xa[2 * i + 0] = ta.x;
            xa[2 * i + 1] = ta.y;
            ulonglong2 tb = pb[i];
            xb[2 * i + 0] = tb.x;
            xb[2 * i + 1] = tb.y;
        }
    }

    // ---- Pass 1: logits (log2 domain). Bias folded into acc init. ----
    float la[MCODE], lb[MCODE];
    #pragma unroll
    for (int m = 0; m < MCODE; m++) {
        const float* s = c_cb.slog[m];
        const u64 binit = cpair(c_cb.b2p[m]);   // (b2, 0)
        u64 s0 = cpair(s + 0),  s1 = cpair(s + 2);
        u64 s2 = cpair(s + 4),  s3 = cpair(s + 6);
        u64 s4 = cpair(s + 8),  s5 = cpair(s + 10);
        u64 s6 = cpair(s + 12), s7 = cpair(s + 14);

        u64 a = fma2(xa[0], s0, binit);
        u64 b = fma2(xb[0], s0, binit);
        a = fma2(xa[1], s1, a);  b = fma2(xb[1], s1, b);
        a = fma2(xa[2], s2, a);  b = fma2(xb[2], s2, b);
        a = fma2(xa[3], s3, a);  b = fma2(xb[3], s3, b);
        a = fma2(xa[4], s4, a);  b = fma2(xb[4], s4, b);
        a = fma2(xa[5], s5, a);  b = fma2(xb[5], s5, b);
        a = fma2(xa[6], s6, a);  b = fma2(xb[6], s6, b);
        a = fma2(xa[7], s7, a);  b = fma2(xb[7], s7, b);

        float lo, hi;
        unpack2(a, lo, hi);
        la[m] = lo + hi;
        unpack2(b, lo, hi);
        lb[m] = lo + hi;
    }

    // ---- max over logits (4 parallel chains each) ----
    float a0 = la[0], a1 = la[1], a2 = la[2], a3 = la[3];
    float d0 = lb[0], d1 = lb[1], d2 = lb[2], d3 = lb[3];
    #pragma unroll
    for (int m = 4; m < MCODE; m += 4) {
        a0 = fmaxf(a0, la[m + 0]);  d0 = fmaxf(d0, lb[m + 0]);
        a1 = fmaxf(a1, la[m + 1]);  d1 = fmaxf(d1, lb[m + 1]);
        a2 = fmaxf(a2, la[m + 2]);  d2 = fmaxf(d2, lb[m + 2]);
        a3 = fmaxf(a3, la[m + 3]);  d3 = fmaxf(d3, lb[m + 3]);
    }
    const float mxa = fmaxf(fmaxf(a0, a1), fmaxf(a2, a3));
    const float mxb = fmaxf(fmaxf(d0, d1), fmaxf(d2, d3));

    // ---- Pass 2: exp + weighted codeword accumulation ----
    float sa0 = 0.0f, sa1 = 0.0f, sb0 = 0.0f, sb1 = 0.0f;
    u64 za[8], zb[8];
    #pragma unroll
    for (int p = 0; p < 8; p++) { za[p] = 0ULL; zb[p] = 0ULL; }

    #pragma unroll
    for (int m = 0; m < MCODE; m++) {
        const float ea = ex2f(la[m] - mxa);
        const float eb = ex2f(lb[m] - mxb);
        if (m & 1) { sa1 += ea; sb1 += eb; }
        else       { sa0 += ea; sb0 += eb; }
        const u64 epa = pack2(ea, ea);
        const u64 epb = pack2(eb, eb);
        const float* w = c_cb.cw[m];
        u64 w0 = cpair(w + 0),  w1 = cpair(w + 2);
        u64 w2 = cpair(w + 4),  w3 = cpair(w + 6);
        u64 w4 = cpair(w + 8),  w5 = cpair(w + 10);
        u64 w6 = cpair(w + 12), w7 = cpair(w + 14);
        za[0] = fma2(epa, w0, za[0]);  zb[0] = fma2(epb, w0, zb[0]);
        za[1] = fma2(epa, w1, za[1]);  zb[1] = fma2(epb, w1, zb[1]);
        za[2] = fma2(epa, w2, za[2]);  zb[2] = fma2(epb, w2, zb[2]);
        za[3] = fma2(epa, w3, za[3]);  zb[3] = fma2(epb, w3, zb[3]);
        za[4] = fma2(epa, w4, za[4]);  zb[4] = fma2(epb, w4, zb[4]);
        za[5] = fma2(epa, w5, za[5]);  zb[5] = fma2(epb, w5, zb[5]);
        za[6] = fma2(epa, w6, za[6]);  zb[6] = fma2(epb, w6, zb[6]);
        za[7] = fma2(epa, w7, za[7]);  zb[7] = fma2(epb, w7, zb[7]);
    }

    // ---- normalize + store ----
    {
        const float inv = rcpf(sa0 + sa1);
        const u64 iv = pack2(inv, inv);
        ulonglong2* o = reinterpret_cast<ulonglong2*>(out + (size_t)v0 * DVEC);
        #pragma unroll
        for (int i = 0; i < 4; i++) {
            ulonglong2 t;
            t.x = mul2(za[2 * i + 0], iv);
            t.y = mul2(za[2 * i + 1], iv);
            o[i] = t;
        }
    }
    {
        const float inv = rcpf(sb0 + sb1);
        const u64 iv = pack2(inv, inv);
        ulonglong2* o = reinterpret_cast<ulonglong2*>(out + (size_t)v1 * DVEC);
        #pragma unroll
        for (int i = 0; i < 4; i++) {
            ulonglong2 t;
            t.x = mul2(zb[2 * i + 0], iv);
            t.y = mul2(zb[2 * i + 1], iv);
            o[i] = t;
        }
    }
}

extern "C" void kernel_launch(void* const* d_in, const int* in_sizes, int n_in,
                              void* d_out, int out_size) {
    const float* x   = (const float*)d_in[0];   // (64,8,32,32,16) f32
    const float* ref = (const float*)d_in[1];   // (64,16) f32
    float* out = (float*)d_out;

    // 1) Prep: scale codebook + biases into staging global.
    prep_kernel<<<1, MCODE>>>(ref);

    // 2) Staging -> __constant__ (device-to-device async copy; capturable).
    void *pc = nullptr, *pg = nullptr;
    cudaGetSymbolAddress(&pc, c_cb);
    cudaGetSymbolAddress(&pg, g_cb);
    cudaMemcpyAsync(pc, pg, sizeof(Codebook), cudaMemcpyDeviceToDevice, 0);

    // 3) Main kernel: 2 vectors per thread.
    const int nvec = in_sizes[0] / DVEC;        // 524288
    const int vecs_per_block = TPB * VPT;
    const int blocks = (nvec + vecs_per_block - 1) / vecs_per_block;
    stq_kernel<<<blocks, TPB>>>(x, out, nvec);
}

// round 7
// speedup vs baseline: 1.1846x; 1.1846x over previous
#include <cuda_runtime.h>
#include <cuda_bf16.h>
#include <cstdint>

// soft_to_hard_quantize: N=524288 vectors of D=16 floats, M=64 codewords.
// logit_m (log2 domain) = 10*log2e*dot(x,r_m) - 5*log2e*||r_m||^2  (||x||^2 cancels)
// z = sum_m exp2(logit_m - max) * r_m / sum_m exp2(...)
//
// Key trick this round: pass 2 reuses the SAME scaled codebook as pass 1
// (r_m = slog_m * ln2/10, folded into the final normalization), and the two
// passes read it through two DIFFERENT hardware ports: pass 1 via the
// constant-bank port (LDC), pass 2 via the shared-memory crossbar (broadcast
// LDS.128). This halves traffic on each port vs. one port serving both passes.

#define MCODE 64
#define DVEC  16
#define TPB   256

typedef unsigned long long u64;

struct Codebook {
    float slog[MCODE][DVEC];  // 10*log2(e) * r_m[i]  (used by BOTH passes)
    float b2p[MCODE][2];      // { -5*log2(e)*||r_m||^2, 0 }  (acc init pair)
};

__device__   Codebook g_cb;   // staging, written by prep kernel
__constant__ Codebook c_cb;   // read by main kernel pass 1

__global__ void prep_kernel(const float* __restrict__ ref) {
    const int m = threadIdx.x;  // 64 threads
    float s = 0.0f;
    #pragma unroll
    for (int i = 0; i < DVEC; i++) {
        float r = ref[m * DVEC + i];
        g_cb.slog[m][i] = 14.426950408889634f * r;   // 10*log2(e)
        s = fmaf(r, r, s);
    }
    g_cb.b2p[m][0] = -7.2134752044448169f * s;       // -5*log2(e)
    g_cb.b2p[m][1] = 0.0f;
}

__device__ __forceinline__ u64 fma2(u64 a, u64 b, u64 c) {
    u64 d;
    asm("fma.rn.f32x2 %0, %1, %2, %3;" : "=l"(d) : "l"(a), "l"(b), "l"(c));
    return d;
}
__device__ __forceinline__ u64 add2(u64 a, u64 b) {
    u64 d;
    asm("add.rn.f32x2 %0, %1, %2;" : "=l"(d) : "l"(a), "l"(b));
    return d;
}
__device__ __forceinline__ u64 mul2(u64 a, u64 b) {
    u64 d;
    asm("mul.rn.f32x2 %0, %1, %2;" : "=l"(d) : "l"(a), "l"(b));
    return d;
}
__device__ __forceinline__ u64 pack2(float lo, float hi) {
    u64 r;
    asm("mov.b64 %0, {%1, %2};" : "=l"(r) : "f"(lo), "f"(hi));
    return r;
}
__device__ __forceinline__ void unpack2(u64 v, float& lo, float& hi) {
    asm("mov.b64 {%0, %1}, %2;" : "=f"(lo), "=f"(hi) : "l"(v));
}
__device__ __forceinline__ float ex2f(float x) {
    float r;
    asm("ex2.approx.ftz.f32 %0, %1;" : "=f"(r) : "f"(x));
    return r;
}
__device__ __forceinline__ float rcpf(float x) {
    float r;
    asm("rcp.approx.ftz.f32 %0, %1;" : "=f"(r) : "f"(x));
    return r;
}
__device__ __forceinline__ u64 cpair(const float* p) {
    return *reinterpret_cast<const u64*>(p);
}

__global__ __launch_bounds__(TPB)
void stq_kernel(const float* __restrict__ x,
                float* __restrict__ out,
                int nvec) {
    // Shared copy of the scaled codebook for pass 2 (separate port from cbank).
    __shared__ __align__(16) float ssl[MCODE * DVEC];

    {
        // 1024 floats = 256 x 16B: one float4 per thread.
        const float4* src = reinterpret_cast<const float4*>(g_cb.slog);
        reinterpret_cast<float4*>(ssl)[threadIdx.x] = src[threadIdx.x];
    }
    __syncthreads();

    const int v = blockIdx.x * TPB + threadIdx.x;
    if (v >= nvec) return;

    // Load this thread's 16-float vector as 8 packed pairs (4 x LDG.128).
    const ulonglong2* xin = reinterpret_cast<const ulonglong2*>(x + (size_t)v * DVEC);
    u64 xp[8];
    #pragma unroll
    for (int i = 0; i < 4; i++) {
        ulonglong2 t = xin[i];
        xp[2 * i + 0] = t.x;
        xp[2 * i + 1] = t.y;
    }

    // ---- Pass 1: logits (log2 domain), codebook via CONSTANT port. ----
    // Two 4-deep FFMA2 chains per m (halved RAW depth), bias in chain-0 init.
    float l[MCODE];
    #pragma unroll
    for (int m = 0; m < MCODE; m++) {
        const float* s = c_cb.slog[m];
        const u64 binit = cpair(c_cb.b2p[m]);   // (b2, 0)
        u64 a0 = fma2(xp[0], cpair(s + 0),  binit);
        u64 a1 = fma2(xp[1], cpair(s + 2),  0ULL);
        a0 = fma2(xp[2], cpair(s + 4),  a0);
        a1 = fma2(xp[3], cpair(s + 6),  a1);
        a0 = fma2(xp[4], cpair(s + 8),  a0);
        a1 = fma2(xp[5], cpair(s + 10), a1);
        a0 = fma2(xp[6], cpair(s + 12), a0);
        a1 = fma2(xp[7], cpair(s + 14), a1);
        u64 acc = add2(a0, a1);
        float lo, hi;
        unpack2(acc, lo, hi);
        l[m] = lo + hi;
    }

    // ---- max over logits (4 parallel chains) ----
    float m0 = l[0], m1 = l[1], m2 = l[2], m3 = l[3];
    #pragma unroll
    for (int m = 4; m < MCODE; m += 4) {
        m0 = fmaxf(m0, l[m + 0]);
        m1 = fmaxf(m1, l[m + 1]);
        m2 = fmaxf(m2, l[m + 2]);
        m3 = fmaxf(m3, l[m + 3]);
    }
    const float mx = fmaxf(fmaxf(m0, m1), fmaxf(m2, m3));

    // ---- Pass 2: exp + weighted accumulation, codebook via SHARED port. ----
    // Accumulates in slog units; ln2/10 scale folded into final inv.
    float s0 = 0.0f, s1 = 0.0f;
    u64 zp[8];
    #pragma unroll
    for (int p = 0; p < 8; p++) zp[p] = 0ULL;

    #pragma unroll
    for (int m = 0; m < MCODE; m++) {
        const float e = ex2f(l[m] - mx);
        if (m & 1) s1 += e; else s0 += e;
        const u64 ee = pack2(e, e);
        const ulonglong2* w = reinterpret_cast<const ulonglong2*>(ssl + m * DVEC);
        ulonglong2 q0 = w[0];
        ulonglong2 q1 = w[1];
        ulonglong2 q2 = w[2];
        ulonglong2 q3 = w[3];
        zp[0] = fma2(ee, q0.x, zp[0]);
        zp[1] = fma2(ee, q0.y, zp[1]);
        zp[2] = fma2(ee, q1.x, zp[2]);
        zp[3] = fma2(ee, q1.y, zp[3]);
        zp[4] = fma2(ee, q2.x, zp[4]);
        zp[5] = fma2(ee, q2.y, zp[5]);
        zp[6] = fma2(ee, q3.x, zp[6]);
        zp[7] = fma2(ee, q3.y, zp[7]);
    }

    // inv = (ln2/10) / sum  — undoes the 10*log2(e) scale baked into slog.
    const float inv = rcpf(s0 + s1) * 0.069314718055994531f;
    const u64 iv = pack2(inv, inv);

    ulonglong2* o = reinterpret_cast<ulonglong2*>(out + (size_t)v * DVEC);
    #pragma unroll
    for (int i = 0; i < 4; i++) {
        ulonglong2 t;
        t.x = mul2(zp[2 * i + 0], iv);
        t.y = mul2(zp[2 * i + 1], iv);
        o[i] = t;
    }
}

extern "C" void kernel_launch(void* const* d_in, const int* in_sizes, int n_in,
                              void* d_out, int out_size) {
    const float* x   = (const float*)d_in[0];   // (64,8,32,32,16) f32
    const float* ref = (const float*)d_in[1];   // (64,16) f32
    float* out = (float*)d_out;

    // 1) Prep: scale codebook + biases into staging global.
    prep_kernel<<<1, MCODE>>>(ref);

    // 2) Staging -> __constant__ (device-to-device async copy; capturable).
    void *pc = nullptr, *pg = nullptr;
    cudaGetSymbolAddress(&pc, c_cb);
    cudaGetSymbolAddress(&pg, g_cb);
    cudaMemcpyAsync(pc, pg, sizeof(Codebook), cudaMemcpyDeviceToDevice, 0);

    // 3) Main kernel.
    const int nvec = in_sizes[0] / DVEC;        // 524288
    const int blocks = (nvec + TPB - 1) / TPB;
    stq_kernel<<<blocks, TPB>>>(x, out, nvec);
}

// round 8
// speedup vs baseline: 1.6101x; 1.3592x over previous
#include <cuda_runtime.h>
#include <cstdint>

// soft_to_hard_quantize via tensor cores (tf32 mma.sync, 3-term split).
//
// logit[v][m] = 14.4269504*dot(x_v, r_m) - 7.2134752*||r_m||^2   (log2 domain)
// e = exp2(logit - rowmax);  z_v = sum_m e*r_m / sum_m e
//
// Pass 1: C[16x64] = X[16x16] * Rs^T  as 8 n-tiles of mma.m16n8k8.tf32.
// Pass 2: Z[16x16] = E[16x64] * R     as 8 k-steps  of mma.m16n8k8.tf32.
// The pass-1 C fragment (m16n8) feeds the pass-2 A fragment (m16k8) directly
// because R's rows are pre-permuted: sigma(8s+q)=8s+2q, sigma(8s+q+4)=8s+2q+1.
// Precision: each operand split v = tf32(v) + tf32(v - tf32(v)); compute
// hi*hi + hi*lo + lo*hi (dropped lo*lo ~ 2^-24).

#define TPB   128   // 4 warps/block, 16 vectors per warp-tile
#define DVEC  16

// Packed codebook tables (built by prep kernel).
__device__ float4 gP1[512];   // [s(2)][m(64)][q(4)] : {h(k=8s+q), h(8s+q+4), l, l} of 14.43*r[m]
__device__ float4 gPB[512];   // [s(8)][j(16)][q(4)] : {h(r[8s+2q][j]), h(r[8s+2q+1][j]), l, l}
__device__ float2 gB2[32];    // [t(8)][q(4)]        : {b2[8t+2q], b2[8t+2q+1]}

__device__ __forceinline__ uint32_t tf32h(float x) {
    uint32_t h; asm("cvt.rna.tf32.f32 %0, %1;" : "=r"(h) : "f"(x)); return h;
}
__device__ __forceinline__ float uf(uint32_t u) { return __uint_as_float(u); }
__device__ __forceinline__ float ex2f(float x) {
    float r; asm("ex2.approx.ftz.f32 %0, %1;" : "=f"(r) : "f"(x)); return r;
}
__device__ __forceinline__ float rcpf(float x) {
    float r; asm("rcp.approx.ftz.f32 %0, %1;" : "=f"(r) : "f"(x)); return r;
}
__device__ __forceinline__ void mma8(float c[4],
                                     uint32_t a0, uint32_t a1, uint32_t a2, uint32_t a3,
                                     uint32_t b0, uint32_t b1) {
    asm volatile(
        "mma.sync.aligned.m16n8k8.row.col.f32.tf32.tf32.f32 "
        "{%0,%1,%2,%3}, {%4,%5,%6,%7}, {%8,%9}, {%0,%1,%2,%3};"
        : "+f"(c[0]), "+f"(c[1]), "+f"(c[2]), "+f"(c[3])
        : "r"(a0), "r"(a1), "r"(a2), "r"(a3), "r"(b0), "r"(b1));
}

__global__ void prep_kernel(const float* __restrict__ ref) {
    const int tid = threadIdx.x;  // 512 threads
    {   // Pass-1 B table: entry (s, m, q)
        const int s = tid >> 8, rem = tid & 255, m = rem >> 2, q = rem & 3;
        const float v0 = 14.426950408889634f * ref[m * DVEC + 8 * s + q];
        const float v1 = 14.426950408889634f * ref[m * DVEC + 8 * s + q + 4];
        const uint32_t h0 = tf32h(v0), h1 = tf32h(v1);
        const uint32_t l0 = tf32h(v0 - uf(h0)), l1 = tf32h(v1 - uf(h1));
        gP1[tid] = make_float4(uf(h0), uf(h1), uf(l0), uf(l1));
    }
    {   // Pass-2 B table: entry (s, j, q), rows permuted by sigma
        const int s = tid >> 6, rem = tid & 63, j = rem >> 2, q = rem & 3;
        const float v0 = ref[(8 * s + 2 * q) * DVEC + j];
        const float v1 = ref[(8 * s + 2 * q + 1) * DVEC + j];
        const uint32_t h0 = tf32h(v0), h1 = tf32h(v1);
        const uint32_t l0 = tf32h(v0 - uf(h0)), l1 = tf32h(v1 - uf(h1));
        gPB[tid] = make_float4(uf(h0), uf(h1), uf(l0), uf(l1));
    }
    if (tid < 32) {  // bias pairs: entry (t, q)
        const int t = tid >> 2, q = tid & 3;
        const int m0 = 8 * t + 2 * q, m1 = m0 + 1;
        float s0 = 0.0f, s1 = 0.0f;
        #pragma unroll
        for (int i = 0; i < DVEC; i++) {
            s0 = fmaf(ref[m0 * DVEC + i], ref[m0 * DVEC + i], s0);
            s1 = fmaf(ref[m1 * DVEC + i], ref[m1 * DVEC + i], s1);
        }
        gB2[tid] = make_float2(-7.2134752044448169f * s0,
                               -7.2134752044448169f * s1);
    }
}

__global__ __launch_bounds__(TPB)
void stq_kernel(const float* __restrict__ x, float* __restrict__ out) {
    __shared__ __align__(16) float4 sP1[512];
    __shared__ __align__(16) float4 sPB[512];
    __shared__ float2 sB2[32];

    const int tid = threadIdx.x;
    #pragma unroll
    for (int i = tid; i < 512; i += TPB) { sP1[i] = gP1[i]; sPB[i] = gPB[i]; }
    if (tid < 32) sB2[tid] = gB2[tid];
    __syncthreads();

    const int warp = tid >> 5;
    const int lane = tid & 31;
    const int g = lane >> 2;     // groupID (row within tile)
    const int q = lane & 3;      // threadID in group

    const int tile = blockIdx.x * 4 + warp;
    const int vg  = tile * 16 + g;       // row g vector index
    const int vg8 = vg + 8;              // row g+8 vector index

    // ---- Load A fragments for pass 1 (x rows), split hi/lo ----
    // kstep s: a0=(g, 8s+q), a1=(g+8, 8s+q), a2=(g, 8s+q+4), a3=(g+8, 8s+q+4)
    uint32_t xh[2][4], xl[2][4];
    {
        const float* xr0 = x + (size_t)vg  * DVEC;
        const float* xr1 = x + (size_t)vg8 * DVEC;
        #pragma unroll
        for (int s = 0; s < 2; s++) {
            float v0 = xr0[8 * s + q];
            float v1 = xr1[8 * s + q];
            float v2 = xr0[8 * s + q + 4];
            float v3 = xr1[8 * s + q + 4];
            xh[s][0] = tf32h(v0); xl[s][0] = tf32h(v0 - uf(xh[s][0]));
            xh[s][1] = tf32h(v1); xl[s][1] = tf32h(v1 - uf(xh[s][1]));
            xh[s][2] = tf32h(v2); xl[s][2] = tf32h(v2 - uf(xh[s][2]));
            xh[s][3] = tf32h(v3); xl[s][3] = tf32h(v3 - uf(xh[s][3]));
        }
    }

    // ---- Pass 1: logits. c[t] = m16n8 tile t (codewords 8t..8t+7) ----
    float c[8][4];
    #pragma unroll
    for (int t = 0; t < 8; t++) { c[t][0] = c[t][1] = c[t][2] = c[t][3] = 0.0f; }

    #pragma unroll
    for (int t = 0; t < 8; t++) {
        #pragma unroll
        for (int s = 0; s < 2; s++) {
            float4 B = sP1[(s * 64 + 8 * t + g) * 4 + q];
            const uint32_t bh0 = __float_as_uint(B.x), bh1 = __float_as_uint(B.y);
            const uint32_t bl0 = __float_as_uint(B.z), bl1 = __float_as_uint(B.w);
            mma8(c[t], xh[s][0], xh[s][1], xh[s][2], xh[s][3], bh0, bh1);
            mma8(c[t], xh[s][0], xh[s][1], xh[s][2], xh[s][3], bl0, bl1);
            mma8(c[t], xl[s][0], xl[s][1], xl[s][2], xl[s][3], bh0, bh1);
        }
    }

    // ---- bias add (per-codeword) ----
    #pragma unroll
    for (int t = 0; t < 8; t++) {
        float2 bb = sB2[t * 4 + q];
        c[t][0] += bb.x; c[t][1] += bb.y;
        c[t][2] += bb.x; c[t][3] += bb.y;
    }

    // ---- row max (row g over c[t][0..1], row g+8 over c[t][2..3]) ----
    float mg = fmaxf(c[0][0], c[0][1]);
    float m8 = fmaxf(c[0][2], c[0][3]);
    #pragma unroll
    for (int t = 1; t < 8; t++) {
        mg = fmaxf(mg, fmaxf(c[t][0], c[t][1]));
        m8 = fmaxf(m8, fmaxf(c[t][2], c[t][3]));
    }
    mg = fmaxf(mg, __shfl_xor_sync(0xffffffffu, mg, 1));
    mg = fmaxf(mg, __shfl_xor_sync(0xffffffffu, mg, 2));
    m8 = fmaxf(m8, __shfl_xor_sync(0xffffffffu, m8, 1));
    m8 = fmaxf(m8, __shfl_xor_sync(0xffffffffu, m8, 2));

    // ---- Pass 2 fused with exp: z = E * R' ----
    float z[2][4];
    z[0][0] = z[0][1] = z[0][2] = z[0][3] = 0.0f;
    z[1][0] = z[1][1] = z[1][2] = z[1][3] = 0.0f;
    float sg = 0.0f, s8 = 0.0f;

    #pragma unroll
    for (int s = 0; s < 8; s++) {
        const float e0 = ex2f(c[s][0] - mg);   // (row g,   m=8s+2q)
        const float e1 = ex2f(c[s][1] - mg);   // (row g,   m=8s+2q+1)
        const float e2 = ex2f(c[s][2] - m8);   // (row g+8, m=8s+2q)
        const float e3 = ex2f(c[s][3] - m8);   // (row g+8, m=8s+2q+1)
        sg += e0 + e1;
        s8 += e2 + e3;
        // A frag for kstep s: a0=(g,k=q)->e0, a1=(g+8,k=q)->e2,
        //                     a2=(g,k=q+4)->e1, a3=(g+8,k=q+4)->e3
        const uint32_t ah0 = tf32h(e0), ah1 = tf32h(e2), ah2 = tf32h(e1), ah3 = tf32h(e3);
        const uint32_t al0 = tf32h(e0 - uf(ah0)), al1 = tf32h(e2 - uf(ah1));
        const uint32_t al2 = tf32h(e1 - uf(ah2)), al3 = tf32h(e3 - uf(ah3));
        #pragma unroll
        for (int nt = 0; nt < 2; nt++) {
            float4 B = sPB[(s * 16 + 8 * nt + g) * 4 + q];
            const uint32_t bh0 = __float_as_uint(B.x), bh1 = __float_as_uint(B.y);
            const uint32_t bl0 = __float_as_uint(B.z), bl1 = __float_as_uint(B.w);
            mma8(z[nt], ah0, ah1, ah2, ah3, bh0, bh1);
            mma8(z[nt], ah0, ah1, ah2, ah3, bl0, bl1);
            mma8(z[nt], al0, al1, al2, al3, bh0, bh1);
        }
    }

    // ---- normalize + store ----
    sg += __shfl_xor_sync(0xffffffffu, sg, 1);
    sg += __shfl_xor_sync(0xffffffffu, sg, 2);
    s8 += __shfl_xor_sync(0xffffffffu, s8, 1);
    s8 += __shfl_xor_sync(0xffffffffu, s8, 2);
    const float ig = rcpf(sg);
    const float i8 = rcpf(s8);

    #pragma unroll
    for (int nt = 0; nt < 2; nt++) {
        float2 r0 = make_float2(z[nt][0] * ig, z[nt][1] * ig);
        float2 r1 = make_float2(z[nt][2] * i8, z[nt][3] * i8);
        *reinterpret_cast<float2*>(out + (size_t)vg  * DVEC + 8 * nt + 2 * q) = r0;
        *reinterpret_cast<float2*>(out + (size_t)vg8 * DVEC + 8 * nt + 2 * q) = r1;
    }
}

extern "C" void kernel_launch(void* const* d_in, const int* in_sizes, int n_in,
                              void* d_out, int out_size) {
    const float* x   = (const float*)d_in[0];   // (64,8,32,32,16) f32
    const float* ref = (const float*)d_in[1];   // (64,16) f32
    float* out = (float*)d_out;

    prep_kernel<<<1, 512>>>(ref);

    const int nvec = in_sizes[0] / DVEC;        // 524288
    const int tiles = nvec / 16;                // 32768
    const int blocks = tiles / 4;               // 8192 (4 warps/block)
    stq_kernel<<<blocks, TPB>>>(x, out);
}